// round 4
// baseline (speedup 1.0000x reference)
#include <cuda_runtime.h>
#include <cuda_fp16.h>

#define N_NODES 100000
#define IN_F    128
#define OUT_F   64
#define E_MAX   1600000

#define SCAN_B  1024
#define N_SCANB ((N_NODES + SCAN_B - 1) / SCAN_B)   // 98

// ------------------------- device scratch (no allocs) -----------------------
__device__ int   g_deg [N_NODES];
__device__ int   g_incl[N_NODES];
__device__ int   g_bsum[N_SCANB];
__device__ int   g_off [N_NODES];
__device__ int   g_cur [N_NODES];
__device__ int   g_adj [E_MAX];
__device__ float g_norm[N_NODES];
__device__ float g_nsq [N_NODES];
// fp16 propagation storage: 64 halves = 32 half2 (uint) per node
__device__ unsigned g_gh [N_NODES * 32];
__device__ unsigned g_h1h[N_NODES * 32];

// ------------------------- degree histogram ---------------------------------
__global__ void deg_kernel(const int* __restrict__ dst, int E) {
    int i = (blockIdx.x * blockDim.x + threadIdx.x) * 4;
    if (i + 3 < E) {
        int4 d = *(const int4*)(dst + i);
        atomicAdd(&g_deg[d.x], 1);
        atomicAdd(&g_deg[d.y], 1);
        atomicAdd(&g_deg[d.z], 1);
        atomicAdd(&g_deg[d.w], 1);
    } else {
        for (int k = i; k < E; k++) atomicAdd(&g_deg[dst[k]], 1);
    }
}

__global__ void norm_kernel() {
    int i = blockIdx.x * blockDim.x + threadIdx.x;
    if (i < N_NODES) {
        int d = g_deg[i];
        float nv = (d > 0) ? rsqrtf((float)d) : 0.0f;
        g_norm[i] = nv;
        g_nsq[i]  = nv * nv;
    }
}

// ------------------------- scan stage 1 --------------------------------------
__global__ void scan1_kernel() {
    __shared__ int s[SCAN_B];
    int tid = threadIdx.x;
    int i = blockIdx.x * SCAN_B + tid;
    int v = (i < N_NODES) ? g_deg[i] : 0;
    s[tid] = v;
    __syncthreads();
#pragma unroll
    for (int off = 1; off < SCAN_B; off <<= 1) {
        int t = (tid >= off) ? s[tid - off] : 0;
        __syncthreads();
        s[tid] += t;
        __syncthreads();
    }
    if (i < N_NODES) g_incl[i] = s[tid];
    if (tid == SCAN_B - 1) g_bsum[blockIdx.x] = s[tid];
}

// ------------------------- scan stages 2+3 fused -----------------------------
// Each block computes its own prefix over g_bsum inline (98 values), then
// writes row offsets + fill cursors for its SCAN_B nodes.
__global__ void scan23_kernel() {
    __shared__ int sb[128];
    __shared__ int s_prefix;
    int tid = threadIdx.x;
    int b = blockIdx.x;

    if (tid < 128) sb[tid] = (tid < N_SCANB) ? g_bsum[tid] : 0;
    __syncthreads();
    if (tid < 32) {
        // sum of sb[t] for t < b, lanes stride 32
        int acc = 0;
        for (int t = tid; t < b; t += 32) acc += sb[t];
#pragma unroll
        for (int o = 16; o > 0; o >>= 1)
            acc += __shfl_xor_sync(0xffffffffu, acc, o);
        if (tid == 0) s_prefix = acc;
    }
    __syncthreads();
    int prefix = s_prefix;

    int i = b * SCAN_B + tid;
    if (i < N_NODES) {
        int start = prefix + g_incl[i] - g_deg[i];
        g_off[i] = start;
        g_cur[i] = start;
    }
}

// ------------------------- CSR fill -----------------------------------------
__global__ void fill_kernel(const int* __restrict__ src,
                            const int* __restrict__ dst, int E) {
    int e = blockIdx.x * blockDim.x + threadIdx.x;
    if (e < E) {
        int pos = atomicAdd(&g_cur[dst[e]], 1);
        g_adj[pos] = src[e];
    }
}

// ------------------------- dense GEMM: g = (feat @ W^T) * norm (fp16 out) ---
#define KP 68
__global__ void gemm_kernel(const float* __restrict__ feat,
                            const float* __restrict__ weight) {
    __shared__ float Ws[IN_F * KP];
    __shared__ float Fs[32 * KP];

    int tid = threadIdx.x;
    for (int p = tid; p < OUT_F * 32; p += 256) {
        int out = p >> 5, jc = p & 31;
        float4 w = ((const float4*)weight)[out * 32 + jc];
        int k = jc * 4;
        Ws[(k + 0) * KP + out] = w.x;
        Ws[(k + 1) * KP + out] = w.y;
        Ws[(k + 2) * KP + out] = w.z;
        Ws[(k + 3) * KP + out] = w.w;
    }

    int nodeBase = blockIdx.x * 64;
    int tx = tid & 15;
    int ty = tid >> 4;
    float acc[4][4] = {};

    for (int kc = 0; kc < IN_F; kc += 32) {
        __syncthreads();
        for (int p = tid; p < 64 * 8; p += 256) {
            int n = p >> 3, jc = p & 7;
            int node = nodeBase + n;
            float4 f = (node < N_NODES)
                ? ((const float4*)feat)[node * 32 + (kc >> 2) + jc]
                : make_float4(0.f, 0.f, 0.f, 0.f);
            int k = jc * 4;
            Fs[(k + 0) * KP + n] = f.x;
            Fs[(k + 1) * KP + n] = f.y;
            Fs[(k + 2) * KP + n] = f.z;
            Fs[(k + 3) * KP + n] = f.w;
        }
        __syncthreads();
#pragma unroll
        for (int k = 0; k < 32; k++) {
            float4 fv = *(const float4*)&Fs[k * KP + ty * 4];
            float4 wv = *(const float4*)&Ws[(kc + k) * KP + tx * 4];
            float f[4] = {fv.x, fv.y, fv.z, fv.w};
            float w[4] = {wv.x, wv.y, wv.z, wv.w};
#pragma unroll
            for (int i = 0; i < 4; i++)
#pragma unroll
                for (int j = 0; j < 4; j++)
                    acc[i][j] += f[i] * w[j];
        }
    }

    uint2* out2 = (uint2*)g_gh;
#pragma unroll
    for (int i = 0; i < 4; i++) {
        int node = nodeBase + ty * 4 + i;
        if (node < N_NODES) {
            float nv = g_norm[node];
            __half2 h0 = __floats2half2_rn(acc[i][0] * nv, acc[i][1] * nv);
            __half2 h1 = __floats2half2_rn(acc[i][2] * nv, acc[i][3] * nv);
            uint2 u;
            u.x = *(unsigned int*)&h0;
            u.y = *(unsigned int*)&h1;
            out2[node * 16 + tx] = u;
        }
    }
}

// ------------------------- gather hops: warp per node -----------------------
// Lane l owns half2 slot l (64 halves/node). Each neighbor = one coalesced
// 128-B row read. Unroll 4 => 4 loads in flight per lane, no shuffles.
__device__ __forceinline__ float2 h2f(unsigned u) {
    return __half22float2(*reinterpret_cast<__half2*>(&u));
}

__global__ void hop1_kernel() {
    int warp = (blockIdx.x * blockDim.x + threadIdx.x) >> 5;
    if (warp >= N_NODES) return;
    int lane = threadIdx.x & 31;
    int node = warp;

    int start = g_off[node];
    int cnt   = g_deg[node];
    const unsigned* __restrict__ base = g_gh;

    float2 acc = {0.f, 0.f};
    int i = 0;
    for (; i + 4 <= cnt; i += 4) {
        int s0 = __ldg(&g_adj[start + i]);
        int s1 = __ldg(&g_adj[start + i + 1]);
        int s2 = __ldg(&g_adj[start + i + 2]);
        int s3 = __ldg(&g_adj[start + i + 3]);
        unsigned v0 = __ldg(&base[s0 * 32 + lane]);
        unsigned v1 = __ldg(&base[s1 * 32 + lane]);
        unsigned v2 = __ldg(&base[s2 * 32 + lane]);
        unsigned v3 = __ldg(&base[s3 * 32 + lane]);
        float2 f0 = h2f(v0), f1 = h2f(v1), f2 = h2f(v2), f3 = h2f(v3);
        acc.x += (f0.x + f1.x) + (f2.x + f3.x);
        acc.y += (f0.y + f1.y) + (f2.y + f3.y);
    }
    for (; i < cnt; i++) {
        int s = __ldg(&g_adj[start + i]);
        float2 f = h2f(__ldg(&base[s * 32 + lane]));
        acc.x += f.x; acc.y += f.y;
    }
    float sc = g_nsq[node];
    __half2 h = __floats2half2_rn(acc.x * sc, acc.y * sc);
    g_h1h[node * 32 + lane] = *(unsigned*)&h;
}

__global__ void hop2_kernel(float* __restrict__ out,
                            const float* __restrict__ bias) {
    int warp = (blockIdx.x * blockDim.x + threadIdx.x) >> 5;
    if (warp >= N_NODES) return;
    int lane = threadIdx.x & 31;
    int node = warp;

    int start = g_off[node];
    int cnt   = g_deg[node];
    const unsigned* __restrict__ base = g_h1h;

    float2 acc = {0.f, 0.f};
    int i = 0;
    for (; i + 4 <= cnt; i += 4) {
        int s0 = __ldg(&g_adj[start + i]);
        int s1 = __ldg(&g_adj[start + i + 1]);
        int s2 = __ldg(&g_adj[start + i + 2]);
        int s3 = __ldg(&g_adj[start + i + 3]);
        unsigned v0 = __ldg(&base[s0 * 32 + lane]);
        unsigned v1 = __ldg(&base[s1 * 32 + lane]);
        unsigned v2 = __ldg(&base[s2 * 32 + lane]);
        unsigned v3 = __ldg(&base[s3 * 32 + lane]);
        float2 f0 = h2f(v0), f1 = h2f(v1), f2 = h2f(v2), f3 = h2f(v3);
        acc.x += (f0.x + f1.x) + (f2.x + f3.x);
        acc.y += (f0.y + f1.y) + (f2.y + f3.y);
    }
    for (; i < cnt; i++) {
        int s = __ldg(&g_adj[start + i]);
        float2 f = h2f(__ldg(&base[s * 32 + lane]));
        acc.x += f.x; acc.y += f.y;
    }
    float sc = g_norm[node];
    float2 b = ((const float2*)bias)[lane];
    float2 r;
    r.x = acc.x * sc + b.x;
    r.y = acc.y * sc + b.y;
    ((float2*)out)[node * 32 + lane] = r;
}

// ----------------------------------------------------------------------------
extern "C" void kernel_launch(void* const* d_in, const int* in_sizes, int n_in,
                              void* d_out, int out_size) {
    const int*   src    = (const int*)  d_in[0];
    const int*   dst    = (const int*)  d_in[1];
    const float* feat   = (const float*)d_in[2];
    const float* weight = (const float*)d_in[3];
    const float* bias   = (const float*)d_in[4];
    float*       out    = (float*)d_out;

    const int E = in_sizes[0];

    // Lazy-created side stream + events (host-side objects, no device allocs)
    static cudaStream_t s2 = nullptr;
    static cudaEvent_t ev_fork = nullptr, ev_join = nullptr;
    if (!s2) {
        cudaStreamCreateWithFlags(&s2, cudaStreamNonBlocking);
        cudaEventCreateWithFlags(&ev_fork, cudaEventDisableTiming);
        cudaEventCreateWithFlags(&ev_join, cudaEventDisableTiming);
    }

    void* deg_ptr;
    cudaGetSymbolAddress(&deg_ptr, g_deg);
    cudaMemsetAsync(deg_ptr, 0, N_NODES * sizeof(int));

    deg_kernel<<<(E / 4 + 255) / 256, 256>>>(dst, E);
    norm_kernel<<<(N_NODES + 255) / 256, 256>>>();

    // Fork: GEMM (depends only on norm) runs concurrently with CSR build
    cudaEventRecord(ev_fork, 0);
    cudaStreamWaitEvent(s2, ev_fork, 0);
    gemm_kernel<<<(N_NODES + 63) / 64, 256, 0, s2>>>(feat, weight);
    cudaEventRecord(ev_join, s2);

    scan1_kernel<<<N_SCANB, SCAN_B>>>();
    scan23_kernel<<<N_SCANB, SCAN_B>>>();
    fill_kernel<<<(E + 255) / 256, 256>>>(src, dst, E);

    cudaStreamWaitEvent(0, ev_join, 0);

    int hop_threads = N_NODES * 32;
    int hop_blocks  = (hop_threads + 255) / 256;
    hop1_kernel<<<hop_blocks, 256>>>();
    hop2_kernel<<<hop_blocks, 256>>>(out, bias);
}

// round 5
// speedup vs baseline: 1.0323x; 1.0323x over previous
#include <cuda_runtime.h>
#include <cuda_fp16.h>

#define N_NODES 100000
#define IN_F    128
#define OUT_F   64
#define E_MAX   1600000

#define SCAN_B  1024
#define N_SCANB ((N_NODES + SCAN_B - 1) / SCAN_B)   // 98

// ------------------------- device scratch (no allocs) -----------------------
__device__ int   g_deg [N_NODES];
__device__ int   g_incl[N_NODES];
__device__ int   g_bsum[N_SCANB];
__device__ int   g_off [N_NODES];
__device__ int   g_cur [N_NODES];
__device__ int   g_adj [E_MAX];
__device__ float g_norm[N_NODES];
__device__ float g_nsq [N_NODES];
// fp16 propagation storage: 64 halves = 8 uint4 per node
__device__ uint4 g_gh [N_NODES * 8];
__device__ uint4 g_h1h[N_NODES * 8];

// ------------------------- degree histogram ---------------------------------
__global__ void deg_kernel(const int* __restrict__ dst, int E) {
    int i = (blockIdx.x * blockDim.x + threadIdx.x) * 4;
    if (i + 3 < E) {
        int4 d = *(const int4*)(dst + i);
        atomicAdd(&g_deg[d.x], 1);
        atomicAdd(&g_deg[d.y], 1);
        atomicAdd(&g_deg[d.z], 1);
        atomicAdd(&g_deg[d.w], 1);
    } else {
        for (int k = i; k < E; k++) atomicAdd(&g_deg[dst[k]], 1);
    }
}

__global__ void norm_kernel() {
    int i = blockIdx.x * blockDim.x + threadIdx.x;
    if (i < N_NODES) {
        int d = g_deg[i];
        float nv = (d > 0) ? rsqrtf((float)d) : 0.0f;
        g_norm[i] = nv;
        g_nsq[i]  = nv * nv;
    }
}

// ------------------------- scan stage 1 --------------------------------------
__global__ void scan1_kernel() {
    __shared__ int s[SCAN_B];
    int tid = threadIdx.x;
    int i = blockIdx.x * SCAN_B + tid;
    int v = (i < N_NODES) ? g_deg[i] : 0;
    s[tid] = v;
    __syncthreads();
#pragma unroll
    for (int off = 1; off < SCAN_B; off <<= 1) {
        int t = (tid >= off) ? s[tid - off] : 0;
        __syncthreads();
        s[tid] += t;
        __syncthreads();
    }
    if (i < N_NODES) g_incl[i] = s[tid];
    if (tid == SCAN_B - 1) g_bsum[blockIdx.x] = s[tid];
}

// ------------------------- scan stages 2+3 fused -----------------------------
__global__ void scan23_kernel() {
    __shared__ int sb[128];
    __shared__ int s_prefix;
    int tid = threadIdx.x;
    int b = blockIdx.x;

    if (tid < 128) sb[tid] = (tid < N_SCANB) ? g_bsum[tid] : 0;
    __syncthreads();
    if (tid < 32) {
        int acc = 0;
        for (int t = tid; t < b; t += 32) acc += sb[t];
#pragma unroll
        for (int o = 16; o > 0; o >>= 1)
            acc += __shfl_xor_sync(0xffffffffu, acc, o);
        if (tid == 0) s_prefix = acc;
    }
    __syncthreads();
    int prefix = s_prefix;

    int i = b * SCAN_B + tid;
    if (i < N_NODES) {
        int start = prefix + g_incl[i] - g_deg[i];
        g_off[i] = start;
        g_cur[i] = start;
    }
}

// ------------------------- CSR fill -----------------------------------------
__global__ void fill_kernel(const int* __restrict__ src,
                            const int* __restrict__ dst, int E) {
    int e = blockIdx.x * blockDim.x + threadIdx.x;
    if (e < E) {
        int pos = atomicAdd(&g_cur[dst[e]], 1);
        g_adj[pos] = src[e];
    }
}

// ------------------------- dense GEMM: g = (feat @ W^T) * norm (fp16 out) ---
#define KP 68
__global__ void gemm_kernel(const float* __restrict__ feat,
                            const float* __restrict__ weight) {
    __shared__ float Ws[IN_F * KP];
    __shared__ float Fs[32 * KP];

    int tid = threadIdx.x;
    for (int p = tid; p < OUT_F * 32; p += 256) {
        int out = p >> 5, jc = p & 31;
        float4 w = ((const float4*)weight)[out * 32 + jc];
        int k = jc * 4;
        Ws[(k + 0) * KP + out] = w.x;
        Ws[(k + 1) * KP + out] = w.y;
        Ws[(k + 2) * KP + out] = w.z;
        Ws[(k + 3) * KP + out] = w.w;
    }

    int nodeBase = blockIdx.x * 64;
    int tx = tid & 15;
    int ty = tid >> 4;
    float acc[4][4] = {};

    for (int kc = 0; kc < IN_F; kc += 32) {
        __syncthreads();
        for (int p = tid; p < 64 * 8; p += 256) {
            int n = p >> 3, jc = p & 7;
            int node = nodeBase + n;
            float4 f = (node < N_NODES)
                ? ((const float4*)feat)[node * 32 + (kc >> 2) + jc]
                : make_float4(0.f, 0.f, 0.f, 0.f);
            int k = jc * 4;
            Fs[(k + 0) * KP + n] = f.x;
            Fs[(k + 1) * KP + n] = f.y;
            Fs[(k + 2) * KP + n] = f.z;
            Fs[(k + 3) * KP + n] = f.w;
        }
        __syncthreads();
#pragma unroll
        for (int k = 0; k < 32; k++) {
            float4 fv = *(const float4*)&Fs[k * KP + ty * 4];
            float4 wv = *(const float4*)&Ws[(kc + k) * KP + tx * 4];
            float f[4] = {fv.x, fv.y, fv.z, fv.w};
            float w[4] = {wv.x, wv.y, wv.z, wv.w};
#pragma unroll
            for (int i = 0; i < 4; i++)
#pragma unroll
                for (int j = 0; j < 4; j++)
                    acc[i][j] += f[i] * w[j];
        }
    }

    uint2* out2 = (uint2*)g_gh;
#pragma unroll
    for (int i = 0; i < 4; i++) {
        int node = nodeBase + ty * 4 + i;
        if (node < N_NODES) {
            float nv = g_norm[node];
            __half2 h0 = __floats2half2_rn(acc[i][0] * nv, acc[i][1] * nv);
            __half2 h1 = __floats2half2_rn(acc[i][2] * nv, acc[i][3] * nv);
            uint2 u;
            u.x = *(unsigned int*)&h0;
            u.y = *(unsigned int*)&h1;
            out2[node * 16 + tx] = u;
        }
    }
}

// ------------------------- gather hops: warp/node, 4 phases x uint4 ---------
// lane = ph*8 + j:  j in 0..7 selects the uint4 quad (16B of the 128B row),
// ph in 0..3 selects the neighbor phase. Each load inst moves 512B/warp;
// 4 rows in flight per warp, x2 unroll = 8.
__device__ __forceinline__ void u4acc(uint4 v, float2* a) {
    float2 f;
    f = __half22float2(*reinterpret_cast<__half2*>(&v.x)); a[0].x += f.x; a[0].y += f.y;
    f = __half22float2(*reinterpret_cast<__half2*>(&v.y)); a[1].x += f.x; a[1].y += f.y;
    f = __half22float2(*reinterpret_cast<__half2*>(&v.z)); a[2].x += f.x; a[2].y += f.y;
    f = __half22float2(*reinterpret_cast<__half2*>(&v.w)); a[3].x += f.x; a[3].y += f.y;
}

__device__ __forceinline__ void phase_reduce(float2* a) {
#pragma unroll
    for (int q = 0; q < 4; q++) {
        a[q].x += __shfl_xor_sync(0xffffffffu, a[q].x, 8);
        a[q].y += __shfl_xor_sync(0xffffffffu, a[q].y, 8);
        a[q].x += __shfl_xor_sync(0xffffffffu, a[q].x, 16);
        a[q].y += __shfl_xor_sync(0xffffffffu, a[q].y, 16);
    }
}

__global__ void hop1_kernel() {
    int node = (blockIdx.x * blockDim.x + threadIdx.x) >> 5;
    if (node >= N_NODES) return;
    int lane = threadIdx.x & 31;
    int j  = lane & 7;
    int ph = lane >> 3;

    int start = g_off[node];
    int cnt   = g_deg[node];

    float2 a[4] = {{0,0},{0,0},{0,0},{0,0}};
    int i = ph;
    for (; i + 4 < cnt; i += 8) {
        int s0 = __ldg(&g_adj[start + i]);
        int s1 = __ldg(&g_adj[start + i + 4]);
        uint4 v0 = __ldg(&g_gh[s0 * 8 + j]);
        uint4 v1 = __ldg(&g_gh[s1 * 8 + j]);
        u4acc(v0, a);
        u4acc(v1, a);
    }
    if (i < cnt) {
        int s = __ldg(&g_adj[start + i]);
        u4acc(__ldg(&g_gh[s * 8 + j]), a);
    }
    phase_reduce(a);
    if (ph == 0) {
        float sc = g_nsq[node];
        __half2 h0 = __floats2half2_rn(a[0].x * sc, a[0].y * sc);
        __half2 h1 = __floats2half2_rn(a[1].x * sc, a[1].y * sc);
        __half2 h2 = __floats2half2_rn(a[2].x * sc, a[2].y * sc);
        __half2 h3 = __floats2half2_rn(a[3].x * sc, a[3].y * sc);
        uint4 u;
        u.x = *(unsigned int*)&h0;
        u.y = *(unsigned int*)&h1;
        u.z = *(unsigned int*)&h2;
        u.w = *(unsigned int*)&h3;
        g_h1h[node * 8 + j] = u;
    }
}

__global__ void hop2_kernel(float* __restrict__ out,
                            const float* __restrict__ bias) {
    int node = (blockIdx.x * blockDim.x + threadIdx.x) >> 5;
    if (node >= N_NODES) return;
    int lane = threadIdx.x & 31;
    int j  = lane & 7;
    int ph = lane >> 3;

    int start = g_off[node];
    int cnt   = g_deg[node];

    float2 a[4] = {{0,0},{0,0},{0,0},{0,0}};
    int i = ph;
    for (; i + 4 < cnt; i += 8) {
        int s0 = __ldg(&g_adj[start + i]);
        int s1 = __ldg(&g_adj[start + i + 4]);
        uint4 v0 = __ldg(&g_h1h[s0 * 8 + j]);
        uint4 v1 = __ldg(&g_h1h[s1 * 8 + j]);
        u4acc(v0, a);
        u4acc(v1, a);
    }
    if (i < cnt) {
        int s = __ldg(&g_adj[start + i]);
        u4acc(__ldg(&g_h1h[s * 8 + j]), a);
    }
    phase_reduce(a);
    if (ph == 0) {
        float sc = g_norm[node];
        const float4* b4 = (const float4*)bias;
        float4 b0 = b4[j * 2], b1 = b4[j * 2 + 1];
        float4 o0, o1;
        o0.x = a[0].x * sc + b0.x;  o0.y = a[0].y * sc + b0.y;
        o0.z = a[1].x * sc + b0.z;  o0.w = a[1].y * sc + b0.w;
        o1.x = a[2].x * sc + b1.x;  o1.y = a[2].y * sc + b1.y;
        o1.z = a[3].x * sc + b1.z;  o1.w = a[3].y * sc + b1.w;
        float4* out4 = (float4*)out;
        out4[node * 16 + j * 2]     = o0;
        out4[node * 16 + j * 2 + 1] = o1;
    }
}

// ----------------------------------------------------------------------------
extern "C" void kernel_launch(void* const* d_in, const int* in_sizes, int n_in,
                              void* d_out, int out_size) {
    const int*   src    = (const int*)  d_in[0];
    const int*   dst    = (const int*)  d_in[1];
    const float* feat   = (const float*)d_in[2];
    const float* weight = (const float*)d_in[3];
    const float* bias   = (const float*)d_in[4];
    float*       out    = (float*)d_out;

    const int E = in_sizes[0];

    static cudaStream_t s2 = nullptr;
    static cudaEvent_t ev_fork = nullptr, ev_join = nullptr;
    if (!s2) {
        cudaStreamCreateWithFlags(&s2, cudaStreamNonBlocking);
        cudaEventCreateWithFlags(&ev_fork, cudaEventDisableTiming);
        cudaEventCreateWithFlags(&ev_join, cudaEventDisableTiming);
    }

    void* deg_ptr;
    cudaGetSymbolAddress(&deg_ptr, g_deg);
    cudaMemsetAsync(deg_ptr, 0, N_NODES * sizeof(int));

    deg_kernel<<<(E / 4 + 255) / 256, 256>>>(dst, E);
    norm_kernel<<<(N_NODES + 255) / 256, 256>>>();

    // Fork: GEMM (depends only on norm) overlaps the CSR build
    cudaEventRecord(ev_fork, 0);
    cudaStreamWaitEvent(s2, ev_fork, 0);
    gemm_kernel<<<(N_NODES + 63) / 64, 256, 0, s2>>>(feat, weight);
    cudaEventRecord(ev_join, s2);

    scan1_kernel<<<N_SCANB, SCAN_B>>>();
    scan23_kernel<<<N_SCANB, SCAN_B>>>();
    fill_kernel<<<(E + 255) / 256, 256>>>(src, dst, E);

    cudaStreamWaitEvent(0, ev_join, 0);

    int hop_threads = N_NODES * 32;
    int hop_blocks  = (hop_threads + 255) / 256;
    hop1_kernel<<<hop_blocks, 256>>>();
    hop2_kernel<<<hop_blocks, 256>>>(out, bias);
}

// round 7
// speedup vs baseline: 1.0652x; 1.0318x over previous
#include <cuda_runtime.h>
#include <cuda_fp16.h>

#define N_NODES 100000
#define IN_F    128
#define OUT_F   64
#define E_MAX   1600000

#define SCAN_B  1024
#define N_SCANB ((N_NODES + SCAN_B - 1) / SCAN_B)   // 98

// ------------------------- device scratch (no allocs) -----------------------
__device__ int   g_deg [N_NODES];
__device__ int   g_incl[N_NODES];
__device__ int   g_bsum[N_SCANB];
__device__ int   g_off [N_NODES];
__device__ int   g_cur [N_NODES];
__device__ int   g_adj [E_MAX];
__device__ float g_norm[N_NODES];
__device__ float g_nsq [N_NODES];
// fp16 propagation storage: 64 halves = 8 uint4 per node (128B row)
__device__ uint4 g_gh [N_NODES * 8];   // UN-normalized feat@W^T
__device__ uint4 g_h1h[N_NODES * 8];   // X[n] = nsq[n] * sum norm[s]*g0[s]

// ------------------------- degree histogram ---------------------------------
__global__ void deg_kernel(const int* __restrict__ dst, int E) {
    int i = (blockIdx.x * blockDim.x + threadIdx.x) * 4;
    if (i + 3 < E) {
        int4 d = *(const int4*)(dst + i);
        atomicAdd(&g_deg[d.x], 1);
        atomicAdd(&g_deg[d.y], 1);
        atomicAdd(&g_deg[d.z], 1);
        atomicAdd(&g_deg[d.w], 1);
    } else {
        for (int k = i; k < E; k++) atomicAdd(&g_deg[dst[k]], 1);
    }
}

// ------------------------- scan1 (warp-scan) + norm fused --------------------
__global__ void scan1_kernel() {
    __shared__ int wsum[32];
    int tid = threadIdx.x;
    int lane = tid & 31;
    int wid = tid >> 5;
    int i = blockIdx.x * SCAN_B + tid;
    int v = (i < N_NODES) ? g_deg[i] : 0;

    // fused norm/nsq
    if (i < N_NODES) {
        float nv = (v > 0) ? rsqrtf((float)v) : 0.0f;
        g_norm[i] = nv;
        g_nsq[i]  = nv * nv;
    }

    // warp inclusive scan
    int x = v;
#pragma unroll
    for (int o = 1; o < 32; o <<= 1) {
        int t = __shfl_up_sync(0xffffffffu, x, o);
        if (lane >= o) x += t;
    }
    if (lane == 31) wsum[wid] = x;
    __syncthreads();
    if (wid == 0) {
        int w = wsum[lane];
#pragma unroll
        for (int o = 1; o < 32; o <<= 1) {
            int t = __shfl_up_sync(0xffffffffu, w, o);
            if (lane >= o) w += t;
        }
        wsum[lane] = w;
    }
    __syncthreads();
    int incl = x + (wid > 0 ? wsum[wid - 1] : 0);
    if (i < N_NODES) g_incl[i] = incl;
    if (tid == SCAN_B - 1) g_bsum[blockIdx.x] = incl;
}

// ------------------------- scan stages 2+3 fused -----------------------------
__global__ void scan23_kernel() {
    __shared__ int sb[128];
    __shared__ int s_prefix;
    int tid = threadIdx.x;
    int b = blockIdx.x;

    if (tid < 128) sb[tid] = (tid < N_SCANB) ? g_bsum[tid] : 0;
    __syncthreads();
    if (tid < 32) {
        int acc = 0;
        for (int t = tid; t < b; t += 32) acc += sb[t];
#pragma unroll
        for (int o = 16; o > 0; o >>= 1)
            acc += __shfl_xor_sync(0xffffffffu, acc, o);
        if (tid == 0) s_prefix = acc;
    }
    __syncthreads();
    int prefix = s_prefix;

    int i = b * SCAN_B + tid;
    if (i < N_NODES) {
        int start = prefix + g_incl[i] - g_deg[i];
        g_off[i] = start;
        g_cur[i] = start;
    }
}

// ------------------------- CSR fill -----------------------------------------
__global__ void fill_kernel(const int* __restrict__ src,
                            const int* __restrict__ dst, int E) {
    int e = blockIdx.x * blockDim.x + threadIdx.x;
    if (e < E) {
        int pos = atomicAdd(&g_cur[dst[e]], 1);
        g_adj[pos] = src[e];
    }
}

// ------------------------- dense GEMM: g0 = feat @ W^T (fp16, NO norm) ------
// Zero-dependency: overlaps the whole CSR build on a side stream.
#define KP 68
__global__ void gemm_kernel(const float* __restrict__ feat,
                            const float* __restrict__ weight) {
    __shared__ float Ws[IN_F * KP];
    __shared__ float Fs[32 * KP];

    int tid = threadIdx.x;
    for (int p = tid; p < OUT_F * 32; p += 256) {
        int out = p >> 5, jc = p & 31;
        float4 w = ((const float4*)weight)[out * 32 + jc];
        int k = jc * 4;
        Ws[(k + 0) * KP + out] = w.x;
        Ws[(k + 1) * KP + out] = w.y;
        Ws[(k + 2) * KP + out] = w.z;
        Ws[(k + 3) * KP + out] = w.w;
    }

    int nodeBase = blockIdx.x * 64;
    int tx = tid & 15;
    int ty = tid >> 4;
    float acc[4][4] = {};

    for (int kc = 0; kc < IN_F; kc += 32) {
        __syncthreads();
        for (int p = tid; p < 64 * 8; p += 256) {
            int n = p >> 3, jc = p & 7;
            int node = nodeBase + n;
            float4 f = (node < N_NODES)
                ? ((const float4*)feat)[node * 32 + (kc >> 2) + jc]
                : make_float4(0.f, 0.f, 0.f, 0.f);
            int k = jc * 4;
            Fs[(k + 0) * KP + n] = f.x;
            Fs[(k + 1) * KP + n] = f.y;
            Fs[(k + 2) * KP + n] = f.z;
            Fs[(k + 3) * KP + n] = f.w;
        }
        __syncthreads();
#pragma unroll
        for (int k = 0; k < 32; k++) {
            float4 fv = *(const float4*)&Fs[k * KP + ty * 4];
            float4 wv = *(const float4*)&Ws[(kc + k) * KP + tx * 4];
            float f[4] = {fv.x, fv.y, fv.z, fv.w};
            float w[4] = {wv.x, wv.y, wv.z, wv.w};
#pragma unroll
            for (int i = 0; i < 4; i++)
#pragma unroll
                for (int j = 0; j < 4; j++)
                    acc[i][j] += f[i] * w[j];
        }
    }

    uint2* out2 = (uint2*)g_gh;
#pragma unroll
    for (int i = 0; i < 4; i++) {
        int node = nodeBase + ty * 4 + i;
        if (node < N_NODES) {
            __half2 h0 = __floats2half2_rn(acc[i][0], acc[i][1]);
            __half2 h1 = __floats2half2_rn(acc[i][2], acc[i][3]);
            uint2 u;
            u.x = *(unsigned int*)&h0;
            u.y = *(unsigned int*)&h1;
            out2[node * 16 + tx] = u;
        }
    }
}

// ------------------------- gather hops: warp/node, 4 phases x uint4 ---------
// lane = ph*8 + j. 4 rows in flight per phase (16 neighbors per warp iter).
__device__ __forceinline__ void u4fma(uint4 v, float ns, float2* a) {
    float2 f;
    f = __half22float2(*reinterpret_cast<__half2*>(&v.x)); a[0].x += f.x * ns; a[0].y += f.y * ns;
    f = __half22float2(*reinterpret_cast<__half2*>(&v.y)); a[1].x += f.x * ns; a[1].y += f.y * ns;
    f = __half22float2(*reinterpret_cast<__half2*>(&v.z)); a[2].x += f.x * ns; a[2].y += f.y * ns;
    f = __half22float2(*reinterpret_cast<__half2*>(&v.w)); a[3].x += f.x * ns; a[3].y += f.y * ns;
}
__device__ __forceinline__ void u4acc(uint4 v, float2* a) {
    float2 f;
    f = __half22float2(*reinterpret_cast<__half2*>(&v.x)); a[0].x += f.x; a[0].y += f.y;
    f = __half22float2(*reinterpret_cast<__half2*>(&v.y)); a[1].x += f.x; a[1].y += f.y;
    f = __half22float2(*reinterpret_cast<__half2*>(&v.z)); a[2].x += f.x; a[2].y += f.y;
    f = __half22float2(*reinterpret_cast<__half2*>(&v.w)); a[3].x += f.x; a[3].y += f.y;
}

__device__ __forceinline__ void phase_reduce(float2* a) {
#pragma unroll
    for (int q = 0; q < 4; q++) {
        a[q].x += __shfl_xor_sync(0xffffffffu, a[q].x, 8);
        a[q].y += __shfl_xor_sync(0xffffffffu, a[q].y, 8);
        a[q].x += __shfl_xor_sync(0xffffffffu, a[q].x, 16);
        a[q].y += __shfl_xor_sync(0xffffffffu, a[q].y, 16);
    }
}

// hop1: X[n] = nsq[n] * sum_{s} norm[s] * g0[s]
__global__ void hop1_kernel() {
    int node = (blockIdx.x * blockDim.x + threadIdx.x) >> 5;
    if (node >= N_NODES) return;
    int lane = threadIdx.x & 31;
    int j  = lane & 7;
    int ph = lane >> 3;

    int start = g_off[node];
    int cnt   = g_deg[node];

    float2 a[4] = {{0,0},{0,0},{0,0},{0,0}};
    int i = ph;
    for (; i + 12 < cnt; i += 16) {
        int s0 = __ldg(&g_adj[start + i]);
        int s1 = __ldg(&g_adj[start + i + 4]);
        int s2 = __ldg(&g_adj[start + i + 8]);
        int s3 = __ldg(&g_adj[start + i + 12]);
        float n0 = __ldg(&g_norm[s0]);
        float n1 = __ldg(&g_norm[s1]);
        float n2 = __ldg(&g_norm[s2]);
        float n3 = __ldg(&g_norm[s3]);
        uint4 v0 = __ldg(&g_gh[s0 * 8 + j]);
        uint4 v1 = __ldg(&g_gh[s1 * 8 + j]);
        uint4 v2 = __ldg(&g_gh[s2 * 8 + j]);
        uint4 v3 = __ldg(&g_gh[s3 * 8 + j]);
        u4fma(v0, n0, a); u4fma(v1, n1, a);
        u4fma(v2, n2, a); u4fma(v3, n3, a);
    }
    for (; i < cnt; i += 4) {
        int s = __ldg(&g_adj[start + i]);
        float ns = __ldg(&g_norm[s]);
        u4fma(__ldg(&g_gh[s * 8 + j]), ns, a);
    }
    phase_reduce(a);
    if (ph == 0) {
        float sc = g_nsq[node];
        __half2 h0 = __floats2half2_rn(a[0].x * sc, a[0].y * sc);
        __half2 h1 = __floats2half2_rn(a[1].x * sc, a[1].y * sc);
        __half2 h2 = __floats2half2_rn(a[2].x * sc, a[2].y * sc);
        __half2 h3 = __floats2half2_rn(a[3].x * sc, a[3].y * sc);
        uint4 u;
        u.x = *(unsigned int*)&h0;
        u.y = *(unsigned int*)&h1;
        u.z = *(unsigned int*)&h2;
        u.w = *(unsigned int*)&h3;
        g_h1h[node * 8 + j] = u;
    }
}

// hop2: out[n] = norm[n] * sum_s X[s] + bias
__global__ void hop2_kernel(float* __restrict__ out,
                            const float* __restrict__ bias) {
    int node = (blockIdx.x * blockDim.x + threadIdx.x) >> 5;
    if (node >= N_NODES) return;
    int lane = threadIdx.x & 31;
    int j  = lane & 7;
    int ph = lane >> 3;

    int start = g_off[node];
    int cnt   = g_deg[node];

    float2 a[4] = {{0,0},{0,0},{0,0},{0,0}};
    int i = ph;
    for (; i + 12 < cnt; i += 16) {
        int s0 = __ldg(&g_adj[start + i]);
        int s1 = __ldg(&g_adj[start + i + 4]);
        int s2 = __ldg(&g_adj[start + i + 8]);
        int s3 = __ldg(&g_adj[start + i + 12]);
        uint4 v0 = __ldg(&g_h1h[s0 * 8 + j]);
        uint4 v1 = __ldg(&g_h1h[s1 * 8 + j]);
        uint4 v2 = __ldg(&g_h1h[s2 * 8 + j]);
        uint4 v3 = __ldg(&g_h1h[s3 * 8 + j]);
        u4acc(v0, a); u4acc(v1, a); u4acc(v2, a); u4acc(v3, a);
    }
    for (; i < cnt; i += 4) {
        int s = __ldg(&g_adj[start + i]);
        u4acc(__ldg(&g_h1h[s * 8 + j]), a);
    }
    phase_reduce(a);
    if (ph == 0) {
        float sc = g_norm[node];
        const float4* b4 = (const float4*)bias;
        float4 b0 = b4[j * 2], b1 = b4[j * 2 + 1];
        float4 o0, o1;
        o0.x = a[0].x * sc + b0.x;  o0.y = a[0].y * sc + b0.y;
        o0.z = a[1].x * sc + b0.z;  o0.w = a[1].y * sc + b0.w;
        o1.x = a[2].x * sc + b1.x;  o1.y = a[2].y * sc + b1.y;
        o1.z = a[3].x * sc + b1.z;  o1.w = a[3].y * sc + b1.w;
        float4* out4 = (float4*)out;
        out4[node * 16 + j * 2]     = o0;
        out4[node * 16 + j * 2 + 1] = o1;
    }
}

// ----------------------------------------------------------------------------
extern "C" void kernel_launch(void* const* d_in, const int* in_sizes, int n_in,
                              void* d_out, int out_size) {
    const int*   src    = (const int*)  d_in[0];
    const int*   dst    = (const int*)  d_in[1];
    const float* feat   = (const float*)d_in[2];
    const float* weight = (const float*)d_in[3];
    const float* bias   = (const float*)d_in[4];
    float*       out    = (float*)d_out;

    const int E = in_sizes[0];

    static cudaStream_t s2 = nullptr;
    static cudaEvent_t ev_fork = nullptr, ev_join = nullptr;
    if (!s2) {
        cudaStreamCreateWithFlags(&s2, cudaStreamNonBlocking);
        cudaEventCreateWithFlags(&ev_fork, cudaEventDisableTiming);
        cudaEventCreateWithFlags(&ev_join, cudaEventDisableTiming);
    }

    // Fork GEMM immediately — it depends on nothing but the inputs.
    cudaEventRecord(ev_fork, 0);
    cudaStreamWaitEvent(s2, ev_fork, 0);
    gemm_kernel<<<(N_NODES + 63) / 64, 256, 0, s2>>>(feat, weight);
    cudaEventRecord(ev_join, s2);

    void* deg_ptr;
    cudaGetSymbolAddress(&deg_ptr, g_deg);
    cudaMemsetAsync(deg_ptr, 0, N_NODES * sizeof(int));

    deg_kernel<<<(E / 4 + 255) / 256, 256>>>(dst, E);
    scan1_kernel<<<N_SCANB, SCAN_B>>>();      // also computes norm/nsq
    scan23_kernel<<<N_SCANB, SCAN_B>>>();
    fill_kernel<<<(E + 255) / 256, 256>>>(src, dst, E);

    cudaStreamWaitEvent(0, ev_join, 0);

    int hop_threads = N_NODES * 32;
    int hop_blocks  = (hop_threads + 255) / 256;
    hop1_kernel<<<hop_blocks, 256>>>();
    hop2_kernel<<<hop_blocks, 256>>>(out, bias);
}

// round 8
// speedup vs baseline: 1.0845x; 1.0181x over previous
#include <cuda_runtime.h>
#include <cuda_fp16.h>

#define N_NODES 100000
#define IN_F    128
#define OUT_F   64
#define E_MAX   1600000

#define SCAN_B  1024
#define N_SCANB ((N_NODES + SCAN_B - 1) / SCAN_B)   // 98

// ------------------------- device scratch (no allocs) -----------------------
__device__ int   g_deg [N_NODES];
__device__ int   g_bsum[N_SCANB];       // block aggregates; -1 = not published
__device__ int   g_off [N_NODES];       // row start; fill bumps it to row end
__device__ int   g_adj [E_MAX];
__device__ float g_norm[N_NODES];
__device__ float g_nsq [N_NODES];
// fp16 rows: 64 halves = 8 uint4 per node (128B)
__device__ uint4 g_gh [N_NODES * 8];    // g0  = feat@W^T (un-normalized)
__device__ uint4 g_g1 [N_NODES * 8];    // g1  = norm[s] * g0[s]
__device__ uint4 g_h1h[N_NODES * 8];    // X[n] = nsq[n] * sum_s g1[s]

// ------------------------- degree histogram ---------------------------------
__global__ void deg_kernel(const int* __restrict__ dst, int E) {
    int i = (blockIdx.x * blockDim.x + threadIdx.x) * 4;
    if (i + 3 < E) {
        int4 d = *(const int4*)(dst + i);
        atomicAdd(&g_deg[d.x], 1);
        atomicAdd(&g_deg[d.y], 1);
        atomicAdd(&g_deg[d.z], 1);
        atomicAdd(&g_deg[d.w], 1);
    } else {
        for (int k = i; k < E; k++) atomicAdd(&g_deg[dst[k]], 1);
    }
}

// ------------------------- fused scan (lookback) + norm ----------------------
// One kernel: block-local scan, publish aggregate, spin-sum predecessors.
// All 98 blocks are resident in wave 1 (<=2 blocks/SM), publish precedes spin.
__global__ void scan_kernel() {
    __shared__ int wsum[32];
    __shared__ int s_prefix;
    int tid  = threadIdx.x;
    int lane = tid & 31;
    int wid  = tid >> 5;
    int b    = blockIdx.x;
    int i    = b * SCAN_B + tid;
    int v    = (i < N_NODES) ? g_deg[i] : 0;

    if (i < N_NODES) {
        float nv = (v > 0) ? rsqrtf((float)v) : 0.0f;
        g_norm[i] = nv;
        g_nsq[i]  = nv * nv;
    }

    // block inclusive scan
    int x = v;
#pragma unroll
    for (int o = 1; o < 32; o <<= 1) {
        int t = __shfl_up_sync(0xffffffffu, x, o);
        if (lane >= o) x += t;
    }
    if (lane == 31) wsum[wid] = x;
    __syncthreads();
    if (wid == 0) {
        int w = wsum[lane];
#pragma unroll
        for (int o = 1; o < 32; o <<= 1) {
            int t = __shfl_up_sync(0xffffffffu, w, o);
            if (lane >= o) w += t;
        }
        wsum[lane] = w;
    }
    __syncthreads();
    int incl = x + (wid > 0 ? wsum[wid - 1] : 0);

    // publish this block's aggregate (value itself is the payload)
    if (tid == SCAN_B - 1) atomicExch(&g_bsum[b], incl);

    // lookback: warp 0 sums predecessors' aggregates
    if (wid == 0) {
        int acc = 0;
        for (int t = lane; t < b; t += 32) {
            int val;
            do { val = atomicAdd(&g_bsum[t], 0); } while (val == -1);
            acc += val;
        }
#pragma unroll
        for (int o = 16; o > 0; o >>= 1)
            acc += __shfl_xor_sync(0xffffffffu, acc, o);
        if (lane == 0) s_prefix = acc;
    }
    __syncthreads();

    if (i < N_NODES) g_off[i] = s_prefix + incl - v;   // row start (= fill cursor)
}

// ------------------------- CSR fill (bumps g_off to row end) -----------------
__global__ void fill_kernel(const int* __restrict__ src,
                            const int* __restrict__ dst, int E) {
    int e = (blockIdx.x * blockDim.x + threadIdx.x) * 2;
    if (e + 1 < E) {
        int2 s = *(const int2*)(src + e);
        int2 d = *(const int2*)(dst + e);
        int p0 = atomicAdd(&g_off[d.x], 1);
        int p1 = atomicAdd(&g_off[d.y], 1);
        g_adj[p0] = s.x;
        g_adj[p1] = s.y;
    } else if (e < E) {
        int pos = atomicAdd(&g_off[dst[e]], 1);
        g_adj[pos] = src[e];
    }
}

// ------------------------- dense GEMM: g0 = feat @ W^T (fp16) ----------------
#define KP 68
__global__ void gemm_kernel(const float* __restrict__ feat,
                            const float* __restrict__ weight) {
    __shared__ float Ws[IN_F * KP];
    __shared__ float Fs[32 * KP];

    int tid = threadIdx.x;
    for (int p = tid; p < OUT_F * 32; p += 256) {
        int out = p >> 5, jc = p & 31;
        float4 w = ((const float4*)weight)[out * 32 + jc];
        int k = jc * 4;
        Ws[(k + 0) * KP + out] = w.x;
        Ws[(k + 1) * KP + out] = w.y;
        Ws[(k + 2) * KP + out] = w.z;
        Ws[(k + 3) * KP + out] = w.w;
    }

    int nodeBase = blockIdx.x * 64;
    int tx = tid & 15;
    int ty = tid >> 4;
    float acc[4][4] = {};

    for (int kc = 0; kc < IN_F; kc += 32) {
        __syncthreads();
        for (int p = tid; p < 64 * 8; p += 256) {
            int n = p >> 3, jc = p & 7;
            int node = nodeBase + n;
            float4 f = (node < N_NODES)
                ? ((const float4*)feat)[node * 32 + (kc >> 2) + jc]
                : make_float4(0.f, 0.f, 0.f, 0.f);
            int k = jc * 4;
            Fs[(k + 0) * KP + n] = f.x;
            Fs[(k + 1) * KP + n] = f.y;
            Fs[(k + 2) * KP + n] = f.z;
            Fs[(k + 3) * KP + n] = f.w;
        }
        __syncthreads();
#pragma unroll
        for (int k = 0; k < 32; k++) {
            float4 fv = *(const float4*)&Fs[k * KP + ty * 4];
            float4 wv = *(const float4*)&Ws[(kc + k) * KP + tx * 4];
            float f[4] = {fv.x, fv.y, fv.z, fv.w};
            float w[4] = {wv.x, wv.y, wv.z, wv.w};
#pragma unroll
            for (int i = 0; i < 4; i++)
#pragma unroll
                for (int j = 0; j < 4; j++)
                    acc[i][j] += f[i] * w[j];
        }
    }

    uint2* out2 = (uint2*)g_gh;
#pragma unroll
    for (int i = 0; i < 4; i++) {
        int node = nodeBase + ty * 4 + i;
        if (node < N_NODES) {
            __half2 h0 = __floats2half2_rn(acc[i][0], acc[i][1]);
            __half2 h1 = __floats2half2_rn(acc[i][2], acc[i][3]);
            uint2 u;
            u.x = *(unsigned int*)&h0;
            u.y = *(unsigned int*)&h1;
            out2[node * 16 + tx] = u;
        }
    }
}

// ------------------------- scale: g1 = norm[node] * g0 (fp32 math) ----------
__global__ void scale_kernel() {
    int idx = blockIdx.x * blockDim.x + threadIdx.x;   // one uint4 each
    if (idx >= N_NODES * 8) return;
    int node = idx >> 3;
    float nv = g_norm[node];
    uint4 v = g_gh[idx];
    float2 f;
    __half2 h;
    f = __half22float2(*reinterpret_cast<__half2*>(&v.x));
    h = __floats2half2_rn(f.x * nv, f.y * nv); v.x = *(unsigned*)&h;
    f = __half22float2(*reinterpret_cast<__half2*>(&v.y));
    h = __floats2half2_rn(f.x * nv, f.y * nv); v.y = *(unsigned*)&h;
    f = __half22float2(*reinterpret_cast<__half2*>(&v.z));
    h = __floats2half2_rn(f.x * nv, f.y * nv); v.z = *(unsigned*)&h;
    f = __half22float2(*reinterpret_cast<__half2*>(&v.w));
    h = __floats2half2_rn(f.x * nv, f.y * nv); v.w = *(unsigned*)&h;
    g_g1[idx] = v;
}

// ------------------------- gather hops: warp/node, 4 phases x uint4 ---------
__device__ __forceinline__ void u4acc(uint4 v, float2* a) {
    float2 f;
    f = __half22float2(*reinterpret_cast<__half2*>(&v.x)); a[0].x += f.x; a[0].y += f.y;
    f = __half22float2(*reinterpret_cast<__half2*>(&v.y)); a[1].x += f.x; a[1].y += f.y;
    f = __half22float2(*reinterpret_cast<__half2*>(&v.z)); a[2].x += f.x; a[2].y += f.y;
    f = __half22float2(*reinterpret_cast<__half2*>(&v.w)); a[3].x += f.x; a[3].y += f.y;
}

__device__ __forceinline__ void phase_reduce(float2* a) {
#pragma unroll
    for (int q = 0; q < 4; q++) {
        a[q].x += __shfl_xor_sync(0xffffffffu, a[q].x, 8);
        a[q].y += __shfl_xor_sync(0xffffffffu, a[q].y, 8);
        a[q].x += __shfl_xor_sync(0xffffffffu, a[q].x, 16);
        a[q].y += __shfl_xor_sync(0xffffffffu, a[q].y, 16);
    }
}

// hop1: X[n] = nsq[n] * sum_s g1[s]
__global__ void hop1_kernel() {
    int node = (blockIdx.x * blockDim.x + threadIdx.x) >> 5;
    if (node >= N_NODES) return;
    int lane = threadIdx.x & 31;
    int j  = lane & 7;
    int ph = lane >> 3;

    int cnt   = g_deg[node];
    int start = g_off[node] - cnt;     // g_off was bumped to row end by fill

    float2 a[4] = {{0,0},{0,0},{0,0},{0,0}};
    int i = ph;
    for (; i + 12 < cnt; i += 16) {
        int s0 = __ldg(&g_adj[start + i]);
        int s1 = __ldg(&g_adj[start + i + 4]);
        int s2 = __ldg(&g_adj[start + i + 8]);
        int s3 = __ldg(&g_adj[start + i + 12]);
        uint4 v0 = __ldg(&g_g1[s0 * 8 + j]);
        uint4 v1 = __ldg(&g_g1[s1 * 8 + j]);
        uint4 v2 = __ldg(&g_g1[s2 * 8 + j]);
        uint4 v3 = __ldg(&g_g1[s3 * 8 + j]);
        u4acc(v0, a); u4acc(v1, a); u4acc(v2, a); u4acc(v3, a);
    }
    for (; i < cnt; i += 4) {
        int s = __ldg(&g_adj[start + i]);
        u4acc(__ldg(&g_g1[s * 8 + j]), a);
    }
    phase_reduce(a);
    if (ph == 0) {
        float sc = g_nsq[node];
        __half2 h0 = __floats2half2_rn(a[0].x * sc, a[0].y * sc);
        __half2 h1 = __floats2half2_rn(a[1].x * sc, a[1].y * sc);
        __half2 h2 = __floats2half2_rn(a[2].x * sc, a[2].y * sc);
        __half2 h3 = __floats2half2_rn(a[3].x * sc, a[3].y * sc);
        uint4 u;
        u.x = *(unsigned int*)&h0;
        u.y = *(unsigned int*)&h1;
        u.z = *(unsigned int*)&h2;
        u.w = *(unsigned int*)&h3;
        g_h1h[node * 8 + j] = u;
    }
}

// hop2: out[n] = norm[n] * sum_s X[s] + bias
__global__ void hop2_kernel(float* __restrict__ out,
                            const float* __restrict__ bias) {
    int node = (blockIdx.x * blockDim.x + threadIdx.x) >> 5;
    if (node >= N_NODES) return;
    int lane = threadIdx.x & 31;
    int j  = lane & 7;
    int ph = lane >> 3;

    int cnt   = g_deg[node];
    int start = g_off[node] - cnt;

    float2 a[4] = {{0,0},{0,0},{0,0},{0,0}};
    int i = ph;
    for (; i + 12 < cnt; i += 16) {
        int s0 = __ldg(&g_adj[start + i]);
        int s1 = __ldg(&g_adj[start + i + 4]);
        int s2 = __ldg(&g_adj[start + i + 8]);
        int s3 = __ldg(&g_adj[start + i + 12]);
        uint4 v0 = __ldg(&g_h1h[s0 * 8 + j]);
        uint4 v1 = __ldg(&g_h1h[s1 * 8 + j]);
        uint4 v2 = __ldg(&g_h1h[s2 * 8 + j]);
        uint4 v3 = __ldg(&g_h1h[s3 * 8 + j]);
        u4acc(v0, a); u4acc(v1, a); u4acc(v2, a); u4acc(v3, a);
    }
    for (; i < cnt; i += 4) {
        int s = __ldg(&g_adj[start + i]);
        u4acc(__ldg(&g_h1h[s * 8 + j]), a);
    }
    phase_reduce(a);
    if (ph == 0) {
        float sc = g_norm[node];
        const float4* b4 = (const float4*)bias;
        float4 b0 = b4[j * 2], b1 = b4[j * 2 + 1];
        float4 o0, o1;
        o0.x = a[0].x * sc + b0.x;  o0.y = a[0].y * sc + b0.y;
        o0.z = a[1].x * sc + b0.z;  o0.w = a[1].y * sc + b0.w;
        o1.x = a[2].x * sc + b1.x;  o1.y = a[2].y * sc + b1.y;
        o1.z = a[3].x * sc + b1.z;  o1.w = a[3].y * sc + b1.w;
        float4* out4 = (float4*)out;
        out4[node * 16 + j * 2]     = o0;
        out4[node * 16 + j * 2 + 1] = o1;
    }
}

// ----------------------------------------------------------------------------
extern "C" void kernel_launch(void* const* d_in, const int* in_sizes, int n_in,
                              void* d_out, int out_size) {
    const int*   src    = (const int*)  d_in[0];
    const int*   dst    = (const int*)  d_in[1];
    const float* feat   = (const float*)d_in[2];
    const float* weight = (const float*)d_in[3];
    const float* bias   = (const float*)d_in[4];
    float*       out    = (float*)d_out;

    const int E = in_sizes[0];

    static cudaStream_t s2 = nullptr;
    static cudaEvent_t ev_fork = nullptr, ev_scan = nullptr, ev_join = nullptr;
    if (!s2) {
        cudaStreamCreateWithFlags(&s2, cudaStreamNonBlocking);
        cudaEventCreateWithFlags(&ev_fork, cudaEventDisableTiming);
        cudaEventCreateWithFlags(&ev_scan, cudaEventDisableTiming);
        cudaEventCreateWithFlags(&ev_join, cudaEventDisableTiming);
    }

    // Fork GEMM immediately (no dependencies).
    cudaEventRecord(ev_fork, 0);
    cudaStreamWaitEvent(s2, ev_fork, 0);
    gemm_kernel<<<(N_NODES + 63) / 64, 256, 0, s2>>>(feat, weight);

    void *deg_ptr, *bsum_ptr;
    cudaGetSymbolAddress(&deg_ptr,  g_deg);
    cudaGetSymbolAddress(&bsum_ptr, g_bsum);
    cudaMemsetAsync(deg_ptr,  0,    N_NODES * sizeof(int));
    cudaMemsetAsync(bsum_ptr, 0xFF, N_SCANB * sizeof(int));   // -1 sentinel

    deg_kernel<<<(E / 4 + 255) / 256, 256>>>(dst, E);
    scan_kernel<<<N_SCANB, SCAN_B>>>();          // norm + offsets, one kernel

    // scale needs norm (scan done) + g0 (gemm done, same stream)
    cudaEventRecord(ev_scan, 0);
    cudaStreamWaitEvent(s2, ev_scan, 0);
    scale_kernel<<<(N_NODES * 8 + 255) / 256, 256, 0, s2>>>();
    cudaEventRecord(ev_join, s2);

    fill_kernel<<<(E / 2 + 255) / 256, 256>>>(src, dst, E);

    cudaStreamWaitEvent(0, ev_join, 0);

    int hop_threads = N_NODES * 32;
    int hop_blocks  = (hop_threads + 255) / 256;
    hop1_kernel<<<hop_blocks, 256>>>();
    hop2_kernel<<<hop_blocks, 256>>>(out, bias);
}